// round 1
// baseline (speedup 1.0000x reference)
#include <cuda_runtime.h>
#include <cuda_bf16.h>
#include <math.h>

// Problem constants
#define BB 2
#define SS 2048
#define HH 16
#define DD 128
#define NSTATE 2048
#define QKV_W (3*HH*DD)   // 6144

// ---------------- scratch (device globals; no runtime alloc) ----------------
__device__ float g_qkv[(size_t)BB * SS * QKV_W];    // [B,S,6144]
__device__ float g_attn[(size_t)BB * SS * HH * DD]; // [B,S,H,D]

// ---------------- SGEMM (NT): C[m,n] = sum_k A[m,k]*B[n,k] (+bias[n]) -------
// A: [M,K] row-major, B: [N,K] row-major. M%128==0, N%128==0, K%16==0.
#define GM_BM 128
#define GM_BN 128
#define GM_BK 16
#define GM_TM 8
#define GM_TN 8

__global__ __launch_bounds__(256, 2)
void sgemm_nt(const float* __restrict__ A, const float* __restrict__ B,
              const float* __restrict__ bias, float* __restrict__ C,
              int M, int N, int K) {
    __shared__ float As[GM_BK][GM_BM + 4];
    __shared__ float Bs[GM_BK][GM_BN + 4];

    const int tid = threadIdx.x;              // 0..255
    const int m0 = blockIdx.y * GM_BM;
    const int n0 = blockIdx.x * GM_BN;
    const int tx = tid % (GM_BN / GM_TN);     // 0..15
    const int ty = tid / (GM_BN / GM_TN);     // 0..15

    // loader mapping: 2048 floats per tile = 512 float4; 256 thr -> 2 each
    const int ldRow = tid >> 2;               // 0..63
    const int ldCol = (tid & 3) * 4;          // 0,4,8,12

    float acc[GM_TM][GM_TN];
#pragma unroll
    for (int i = 0; i < GM_TM; i++)
#pragma unroll
        for (int j = 0; j < GM_TN; j++) acc[i][j] = 0.f;

    for (int k0 = 0; k0 < K; k0 += GM_BK) {
#pragma unroll
        for (int t = 0; t < 2; t++) {
            int r = ldRow + t * 64;
            float4 va = *(const float4*)&A[(size_t)(m0 + r) * K + k0 + ldCol];
            As[ldCol + 0][r] = va.x; As[ldCol + 1][r] = va.y;
            As[ldCol + 2][r] = va.z; As[ldCol + 3][r] = va.w;
            float4 vb = *(const float4*)&B[(size_t)(n0 + r) * K + k0 + ldCol];
            Bs[ldCol + 0][r] = vb.x; Bs[ldCol + 1][r] = vb.y;
            Bs[ldCol + 2][r] = vb.z; Bs[ldCol + 3][r] = vb.w;
        }
        __syncthreads();

#pragma unroll
        for (int k = 0; k < GM_BK; k++) {
            float ra[GM_TM], rb[GM_TN];
#pragma unroll
            for (int i = 0; i < GM_TM; i++) ra[i] = As[k][ty * GM_TM + i];
#pragma unroll
            for (int j = 0; j < GM_TN; j++) rb[j] = Bs[k][tx * GM_TN + j];
#pragma unroll
            for (int i = 0; i < GM_TM; i++)
#pragma unroll
                for (int j = 0; j < GM_TN; j++)
                    acc[i][j] += ra[i] * rb[j];
        }
        __syncthreads();
    }

#pragma unroll
    for (int i = 0; i < GM_TM; i++) {
        int m = m0 + ty * GM_TM + i;
#pragma unroll
        for (int j = 0; j < GM_TN; j += 4) {
            int n = n0 + tx * GM_TN + j;
            float4 v;
            v.x = acc[i][j + 0]; v.y = acc[i][j + 1];
            v.z = acc[i][j + 2]; v.w = acc[i][j + 3];
            if (bias) {
                float4 bv = *(const float4*)&bias[n];
                v.x += bv.x; v.y += bv.y; v.z += bv.z; v.w += bv.w;
            }
            *(float4*)&C[(size_t)m * N + n] = v;
        }
    }
}

// ---------------- RoPE (q in place, k -> out_k), v copy ---------------------
// one thread per (b*s, h, d2<64)
__global__ void rope_scatter(float* __restrict__ qkv,
                             const float* __restrict__ f_r,
                             const float* __restrict__ f_i,
                             float* __restrict__ out_k,
                             float* __restrict__ out_v) {
    int idx = blockIdx.x * blockDim.x + threadIdx.x;
    if (idx >= BB * SS * HH * 64) return;
    int d2 = idx & 63;
    int h  = (idx >> 6) & (HH - 1);
    int bs = idx >> 10;                   // b*S + s

    float fr = f_r[(size_t)bs * 64 + d2];
    float fi = f_i[(size_t)bs * 64 + d2];

    size_t base = (size_t)bs * QKV_W;
    // q (rope in place)
    size_t qi = base + (size_t)h * DD + d2;
    float xr = qkv[qi], xi = qkv[qi + 64];
    qkv[qi]      = xr * fr - xi * fi;
    qkv[qi + 64] = xr * fi + xi * fr;
    // k (rope -> out_k)
    size_t ki = base + (size_t)HH * DD + (size_t)h * DD + d2;
    xr = qkv[ki]; xi = qkv[ki + 64];
    size_t ko = ((size_t)bs * HH + h) * DD + d2;
    out_k[ko]      = xr * fr - xi * fi;
    out_k[ko + 64] = xr * fi + xi * fr;
    // v copy -> out_v
    size_t vi = base + (size_t)2 * HH * DD + (size_t)h * DD + d2;
    out_v[ko]      = qkv[vi];
    out_v[ko + 64] = qkv[vi + 64];
}

// ---------------- Flash attention (fp32, 64x64 tiles, mask from gmem) -------
// grid: (S/64, H, B); block: 256 threads (8 warps, each warp owns 8 q-rows)
#define FA_KPAD 132          // Ks row stride (pad 4)
#define FA_PPAD 68           // Ps row stride
#define FA_SMEM_FLOATS (64*128 /*Q*/ + 64*FA_KPAD /*K*/ + 64*128 /*V*/ + 8*8*FA_PPAD /*P*/)
#define FA_SMEM_BYTES (FA_SMEM_FLOATS * 4)

__global__ __launch_bounds__(256, 1)
void flash_attn(const float* __restrict__ qkv,
                const float* __restrict__ kbuf,
                const float* __restrict__ vbuf,
                const float* __restrict__ mask,
                float* __restrict__ attn_out) {
    extern __shared__ float sm[];
    float* Qs = sm;                          // [64][128]
    float* Ks = Qs + 64 * 128;               // [64][132]
    float* Vs = Ks + 64 * FA_KPAD;           // [64][128]
    float* Ps = Vs + 64 * 128;               // [8 warps][8][68]

    const int qb = blockIdx.x, h = blockIdx.y, b = blockIdx.z;
    const int tid = threadIdx.x, w = tid >> 5, l = tid & 31;
    const float scale = 0.08838834764831845f;   // 1/sqrt(128)

    // load Q tile, prescaled
    for (int t = tid; t < 64 * 32; t += 256) {
        int r = t >> 5; int c4 = (t & 31) * 4;
        const float* src = &qkv[((size_t)b * SS + qb * 64 + r) * QKV_W + h * DD + c4];
        float4 v = *(const float4*)src;
        v.x *= scale; v.y *= scale; v.z *= scale; v.w *= scale;
        *(float4*)&Qs[r * 128 + c4] = v;
    }

    float O[8][4];
    float m_old[8], lsum[8];
#pragma unroll
    for (int i = 0; i < 8; i++) {
        m_old[i] = -INFINITY; lsum[i] = 0.f;
#pragma unroll
        for (int c = 0; c < 4; c++) O[i][c] = 0.f;
    }

    const int r0 = w * 8;
    float* Pw = Ps + w * 8 * FA_PPAD;
    const int j0 = l, j1 = l + 32;

    for (int kb = 0; kb < SS / 64; kb++) {
        __syncthreads();   // previous iter's K/V/P reads done
        for (int t = tid; t < 64 * 32; t += 256) {
            int r = t >> 5; int c4 = (t & 31) * 4;
            size_t src = ((size_t)b * SS + kb * 64 + r) * (HH * DD) + (size_t)h * DD + c4;
            *(float4*)&Ks[r * FA_KPAD + c4] = *(const float4*)&kbuf[src];
            *(float4*)&Vs[r * 128 + c4]     = *(const float4*)&vbuf[src];
        }
        __syncthreads();

        // ---- scores: each lane owns keys j0, j1 for its warp's 8 rows ----
        float s0[8], s1[8];
#pragma unroll
        for (int i = 0; i < 8; i++) { s0[i] = 0.f; s1[i] = 0.f; }
#pragma unroll 4
        for (int d = 0; d < 128; d += 4) {
            float4 k0 = *(const float4*)&Ks[j0 * FA_KPAD + d];
            float4 k1 = *(const float4*)&Ks[j1 * FA_KPAD + d];
#pragma unroll
            for (int i = 0; i < 8; i++) {
                float4 q = *(const float4*)&Qs[(r0 + i) * 128 + d];
                s0[i] += q.x * k0.x + q.y * k0.y + q.z * k0.z + q.w * k0.w;
                s1[i] += q.x * k1.x + q.y * k1.y + q.z * k1.z + q.w * k1.w;
            }
        }

        // ---- mask + online softmax per row ----
#pragma unroll
        for (int i = 0; i < 8; i++) {
            int q_glob = qb * 64 + r0 + i;
            const float* mrow = &mask[((size_t)b * SS + q_glob) * SS + kb * 64];
            float a0 = s0[i] + mrow[j0];
            float a1 = s1[i] + mrow[j1];
            float mx = fmaxf(a0, a1);
#pragma unroll
            for (int off = 16; off; off >>= 1)
                mx = fmaxf(mx, __shfl_xor_sync(0xffffffff, mx, off));
            float m_new = fmaxf(m_old[i], mx);
            float p0 = __expf(a0 - m_new);
            float p1 = __expf(a1 - m_new);
            float ls = p0 + p1;
#pragma unroll
            for (int off = 16; off; off >>= 1)
                ls += __shfl_xor_sync(0xffffffff, ls, off);
            float alpha = __expf(m_old[i] - m_new);
            lsum[i] = lsum[i] * alpha + ls;
            m_old[i] = m_new;
#pragma unroll
            for (int c = 0; c < 4; c++) O[i][c] *= alpha;
            Pw[i * FA_PPAD + j0] = p0;
            Pw[i * FA_PPAD + j1] = p1;
        }
        __syncwarp();

        // ---- PV: lane owns output cols [4l, 4l+4) ----
#pragma unroll 2
        for (int j = 0; j < 64; j += 4) {
            float4 v0 = *(const float4*)&Vs[(j + 0) * 128 + l * 4];
            float4 v1 = *(const float4*)&Vs[(j + 1) * 128 + l * 4];
            float4 v2 = *(const float4*)&Vs[(j + 2) * 128 + l * 4];
            float4 v3 = *(const float4*)&Vs[(j + 3) * 128 + l * 4];
#pragma unroll
            for (int i = 0; i < 8; i++) {
                float4 p = *(const float4*)&Pw[i * FA_PPAD + j];
                O[i][0] += p.x * v0.x + p.y * v1.x + p.z * v2.x + p.w * v3.x;
                O[i][1] += p.x * v0.y + p.y * v1.y + p.z * v2.y + p.w * v3.y;
                O[i][2] += p.x * v0.z + p.y * v1.z + p.z * v2.z + p.w * v3.z;
                O[i][3] += p.x * v0.w + p.y * v1.w + p.z * v2.w + p.w * v3.w;
            }
        }
    }

    // epilogue: normalize, write [B,S,H,D]
#pragma unroll
    for (int i = 0; i < 8; i++) {
        float inv = 1.0f / lsum[i];
        int q_glob = qb * 64 + r0 + i;
        float4 v;
        v.x = O[i][0] * inv; v.y = O[i][1] * inv;
        v.z = O[i][2] * inv; v.w = O[i][3] * inv;
        *(float4*)&attn_out[(((size_t)b * SS + q_glob) * HH + h) * DD + l * 4] = v;
    }
}

// ---------------- launch ----------------------------------------------------
extern "C" void kernel_launch(void* const* d_in, const int* in_sizes, int n_in,
                              void* d_out, int out_size) {
    const float* x      = (const float*)d_in[0];
    const float* f_r    = (const float*)d_in[1];
    const float* f_i    = (const float*)d_in[2];
    const float* mask   = (const float*)d_in[3];
    const float* W_qkv  = (const float*)d_in[4];
    const float* b_qkv  = (const float*)d_in[5];
    const float* W_o    = (const float*)d_in[6];

    float* out   = (float*)d_out;                         // [B,S,2048]
    float* out_k = out   + (size_t)BB * SS * NSTATE;      // [B,S,H,D]
    float* out_v = out_k + (size_t)BB * SS * HH * DD;     // [B,S,H,D]

    float* qkv  = nullptr; cudaGetSymbolAddress((void**)&qkv,  g_qkv);
    float* attn = nullptr; cudaGetSymbolAddress((void**)&attn, g_attn);

    const int M = BB * SS;   // 4096

    // 1) QKV projection: [4096,6144] = x @ W_qkv^T + b
    sgemm_nt<<<dim3(QKV_W / GM_BN, M / GM_BM), 256>>>(x, W_qkv, b_qkv, qkv,
                                                      M, QKV_W, NSTATE);
    // 2) RoPE q,k; scatter k,v to output
    rope_scatter<<<(BB * SS * HH * 64) / 256, 256>>>(qkv, f_r, f_i, out_k, out_v);

    // 3) attention
    cudaFuncSetAttribute(flash_attn, cudaFuncAttributeMaxDynamicSharedMemorySize,
                         FA_SMEM_BYTES);
    flash_attn<<<dim3(SS / 64, HH, BB), 256, FA_SMEM_BYTES>>>(qkv, out_k, out_v,
                                                              mask, attn);
    // 4) output projection: [4096,2048] = attn @ W_o^T
    sgemm_nt<<<dim3(NSTATE / GM_BN, M / GM_BM), 256>>>(attn, W_o, nullptr, out,
                                                       M, NSTATE, NSTATE);
}

// round 3
// speedup vs baseline: 2.2588x; 2.2588x over previous
#include <cuda_runtime.h>
#include <cuda_bf16.h>
#include <cstdint>
#include <math.h>

// Problem constants
#define BB 2
#define SS 2048
#define HH 16
#define DD 128
#define NSTATE 2048
#define QKV_W (3*HH*DD)   // 6144

// ---------------- scratch (device globals; no runtime alloc) ----------------
__device__ float g_qkv[(size_t)BB * SS * QKV_W];    // [B,S,6144]
__device__ float g_attn[(size_t)BB * SS * HH * DD]; // [B,S,H,D]

// ---------------- helpers ----------------------------------------------------
__device__ __forceinline__ uint32_t tf32_rna(float x) {
    uint32_t r; asm("cvt.rna.tf32.f32 %0, %1;" : "=r"(r) : "f"(x)); return r;
}
__device__ __forceinline__ void mma_tf32_16x8x8(float* c, const uint32_t* a,
                                                const uint32_t* b) {
    asm volatile(
        "mma.sync.aligned.m16n8k8.row.col.f32.tf32.tf32.f32 "
        "{%0,%1,%2,%3}, {%4,%5,%6,%7}, {%8,%9}, {%0,%1,%2,%3};\n"
        : "+f"(c[0]), "+f"(c[1]), "+f"(c[2]), "+f"(c[3])
        : "r"(a[0]), "r"(a[1]), "r"(a[2]), "r"(a[3]), "r"(b[0]), "r"(b[1]));
}

// ============================================================================
// tf32 mma.sync GEMM (NT): C[m,n] = sum_k A[m,k]*B[n,k] (+bias[n])
// A: [M,K] row-major, B: [N,K] row-major. M%128==0, N%128==0, K%16==0.
// Block tile 128x128x16, 8 warps (4x2), warp tile 32x64, double-buffered smem.
// ============================================================================
#define TPAD 20   // smem row stride (16 + 4): conflict-free fragment loads

__global__ __launch_bounds__(256, 2)
void gemm_mma(const float* __restrict__ A, const float* __restrict__ B,
              const float* __restrict__ bias, float* __restrict__ C,
              int M, int N, int K) {
    __shared__ uint32_t As[2][128 * TPAD];
    __shared__ uint32_t Bs[2][128 * TPAD];

    const int tid = threadIdx.x;
    const int w = tid >> 5, l = tid & 31;
    const int lr = l >> 2, lc = l & 3;
    const int wm = w >> 1, wn = w & 1;           // warps 4 (m) x 2 (n)
    const int m0 = blockIdx.y * 128, n0 = blockIdx.x * 128;

    // loader mapping: 512 float4 per tile, 2 per thread (rows r and r+64)
    const int row = tid >> 2;
    const int c4  = (tid & 3) * 4;

    float acc[2][8][4];
#pragma unroll
    for (int mt = 0; mt < 2; mt++)
#pragma unroll
        for (int nt = 0; nt < 8; nt++)
#pragma unroll
            for (int i = 0; i < 4; i++) acc[mt][nt][i] = 0.f;

    float4 pa0, pa1, pb0, pb1;
    const int NC = K / 16;

    // prologue: load chunk 0
    pa0 = *(const float4*)&A[(size_t)(m0 + row) * K + c4];
    pa1 = *(const float4*)&A[(size_t)(m0 + row + 64) * K + c4];
    pb0 = *(const float4*)&B[(size_t)(n0 + row) * K + c4];
    pb1 = *(const float4*)&B[(size_t)(n0 + row + 64) * K + c4];
    {
        uint32_t* a = As[0]; uint32_t* b = Bs[0];
        a[row * TPAD + c4 + 0] = tf32_rna(pa0.x); a[row * TPAD + c4 + 1] = tf32_rna(pa0.y);
        a[row * TPAD + c4 + 2] = tf32_rna(pa0.z); a[row * TPAD + c4 + 3] = tf32_rna(pa0.w);
        a[(row + 64) * TPAD + c4 + 0] = tf32_rna(pa1.x); a[(row + 64) * TPAD + c4 + 1] = tf32_rna(pa1.y);
        a[(row + 64) * TPAD + c4 + 2] = tf32_rna(pa1.z); a[(row + 64) * TPAD + c4 + 3] = tf32_rna(pa1.w);
        b[row * TPAD + c4 + 0] = tf32_rna(pb0.x); b[row * TPAD + c4 + 1] = tf32_rna(pb0.y);
        b[row * TPAD + c4 + 2] = tf32_rna(pb0.z); b[row * TPAD + c4 + 3] = tf32_rna(pb0.w);
        b[(row + 64) * TPAD + c4 + 0] = tf32_rna(pb1.x); b[(row + 64) * TPAD + c4 + 1] = tf32_rna(pb1.y);
        b[(row + 64) * TPAD + c4 + 2] = tf32_rna(pb1.z); b[(row + 64) * TPAD + c4 + 3] = tf32_rna(pb1.w);
    }
    __syncthreads();

    const int aBase = (wm * 32 + lr) * TPAD;
    const int bBase = (wn * 64 + lr) * TPAD;

    for (int c = 0; c < NC; c++) {
        const int buf = c & 1;
        if (c + 1 < NC) {                 // prefetch next chunk into registers
            const int k0 = (c + 1) * 16;
            pa0 = *(const float4*)&A[(size_t)(m0 + row) * K + k0 + c4];
            pa1 = *(const float4*)&A[(size_t)(m0 + row + 64) * K + k0 + c4];
            pb0 = *(const float4*)&B[(size_t)(n0 + row) * K + k0 + c4];
            pb1 = *(const float4*)&B[(size_t)(n0 + row + 64) * K + k0 + c4];
        }

        const uint32_t* __restrict__ a_s = As[buf];
        const uint32_t* __restrict__ b_s = Bs[buf];
#pragma unroll
        for (int kk = 0; kk < 16; kk += 8) {
            uint32_t af[2][4];
#pragma unroll
            for (int mt = 0; mt < 2; mt++) {
                int o = aBase + mt * (16 * TPAD) + kk + lc;
                af[mt][0] = a_s[o];
                af[mt][1] = a_s[o + 8 * TPAD];
                af[mt][2] = a_s[o + 4];
                af[mt][3] = a_s[o + 8 * TPAD + 4];
            }
            uint32_t bf[8][2];
#pragma unroll
            for (int nt = 0; nt < 8; nt++) {
                int o = bBase + nt * (8 * TPAD) + kk + lc;
                bf[nt][0] = b_s[o];
                bf[nt][1] = b_s[o + 4];
            }
#pragma unroll
            for (int mt = 0; mt < 2; mt++)
#pragma unroll
                for (int nt = 0; nt < 8; nt++)
                    mma_tf32_16x8x8(acc[mt][nt], af[mt], bf[nt]);
        }
        __syncthreads();

        if (c + 1 < NC) {
            const int nb = (c + 1) & 1;
            uint32_t* a = As[nb]; uint32_t* b = Bs[nb];
            a[row * TPAD + c4 + 0] = tf32_rna(pa0.x); a[row * TPAD + c4 + 1] = tf32_rna(pa0.y);
            a[row * TPAD + c4 + 2] = tf32_rna(pa0.z); a[row * TPAD + c4 + 3] = tf32_rna(pa0.w);
            a[(row + 64) * TPAD + c4 + 0] = tf32_rna(pa1.x); a[(row + 64) * TPAD + c4 + 1] = tf32_rna(pa1.y);
            a[(row + 64) * TPAD + c4 + 2] = tf32_rna(pa1.z); a[(row + 64) * TPAD + c4 + 3] = tf32_rna(pa1.w);
            b[row * TPAD + c4 + 0] = tf32_rna(pb0.x); b[row * TPAD + c4 + 1] = tf32_rna(pb0.y);
            b[row * TPAD + c4 + 2] = tf32_rna(pb0.z); b[row * TPAD + c4 + 3] = tf32_rna(pb0.w);
            b[(row + 64) * TPAD + c4 + 0] = tf32_rna(pb1.x); b[(row + 64) * TPAD + c4 + 1] = tf32_rna(pb1.y);
            b[(row + 64) * TPAD + c4 + 2] = tf32_rna(pb1.z); b[(row + 64) * TPAD + c4 + 3] = tf32_rna(pb1.w);
            __syncthreads();
        }
    }

    // epilogue: D layout per mma: d0,d1 -> (row, 2*lc..+1), d2,d3 -> (row+8, ..)
#pragma unroll
    for (int mt = 0; mt < 2; mt++) {
        int m = m0 + wm * 32 + mt * 16 + lr;
#pragma unroll
        for (int nt = 0; nt < 8; nt++) {
            int n = n0 + wn * 64 + nt * 8 + lc * 2;
            float bx = 0.f, by = 0.f;
            if (bias) { bx = bias[n]; by = bias[n + 1]; }
            float2 v0 = { acc[mt][nt][0] + bx, acc[mt][nt][1] + by };
            float2 v1 = { acc[mt][nt][2] + bx, acc[mt][nt][3] + by };
            *(float2*)&C[(size_t)m * N + n] = v0;
            *(float2*)&C[(size_t)(m + 8) * N + n] = v1;
        }
    }
}

// ---------------- RoPE (q in place, k -> out_k), v copy ---------------------
__global__ void rope_scatter(float* __restrict__ qkv,
                             const float* __restrict__ f_r,
                             const float* __restrict__ f_i,
                             float* __restrict__ out_k,
                             float* __restrict__ out_v) {
    int idx = blockIdx.x * blockDim.x + threadIdx.x;
    if (idx >= BB * SS * HH * 64) return;
    int d2 = idx & 63;
    int h  = (idx >> 6) & (HH - 1);
    int bs = idx >> 10;

    float fr = f_r[(size_t)bs * 64 + d2];
    float fi = f_i[(size_t)bs * 64 + d2];

    size_t base = (size_t)bs * QKV_W;
    size_t qi = base + (size_t)h * DD + d2;
    float xr = qkv[qi], xi = qkv[qi + 64];
    qkv[qi]      = xr * fr - xi * fi;
    qkv[qi + 64] = xr * fi + xi * fr;

    size_t ki = base + (size_t)HH * DD + (size_t)h * DD + d2;
    xr = qkv[ki]; xi = qkv[ki + 64];
    size_t ko = ((size_t)bs * HH + h) * DD + d2;
    out_k[ko]      = xr * fr - xi * fi;
    out_k[ko + 64] = xr * fi + xi * fr;

    size_t vi = base + (size_t)2 * HH * DD + (size_t)h * DD + d2;
    out_v[ko]      = qkv[vi];
    out_v[ko + 64] = qkv[vi + 64];
}

// ---------------- Flash attention (fp32, 64x64 tiles, causal block skip) ----
#define FA_KPAD 132
#define FA_PPAD 68
#define FA_SMEM_FLOATS (64*128 + 64*FA_KPAD + 64*128 + 8*8*FA_PPAD)
#define FA_SMEM_BYTES (FA_SMEM_FLOATS * 4)

__global__ __launch_bounds__(256, 1)
void flash_attn(const float* __restrict__ qkv,
                const float* __restrict__ kbuf,
                const float* __restrict__ vbuf,
                const float* __restrict__ mask,
                float* __restrict__ attn_out) {
    extern __shared__ float smf[];
    float* Qs = smf;
    float* Ks = Qs + 64 * 128;
    float* Vs = Ks + 64 * FA_KPAD;
    float* Ps = Vs + 64 * 128;

    const int qb = blockIdx.x, h = blockIdx.y, b = blockIdx.z;
    const int tid = threadIdx.x, w = tid >> 5, l = tid & 31;
    const float scale = 0.08838834764831845f;

    for (int t = tid; t < 64 * 32; t += 256) {
        int r = t >> 5; int c4 = (t & 31) * 4;
        const float* src = &qkv[((size_t)b * SS + qb * 64 + r) * QKV_W + h * DD + c4];
        float4 v = *(const float4*)src;
        v.x *= scale; v.y *= scale; v.z *= scale; v.w *= scale;
        *(float4*)&Qs[r * 128 + c4] = v;
    }

    float O[8][4];
    float m_old[8], lsum[8];
#pragma unroll
    for (int i = 0; i < 8; i++) {
        m_old[i] = -INFINITY; lsum[i] = 0.f;
#pragma unroll
        for (int c = 0; c < 4; c++) O[i][c] = 0.f;
    }

    const int r0 = w * 8;
    float* Pw = Ps + w * 8 * FA_PPAD;
    const int j0 = l, j1 = l + 32;

    // causal: kv blocks strictly above the diagonal are fully masked -> skip
    for (int kb = 0; kb <= qb; kb++) {
        __syncthreads();
        for (int t = tid; t < 64 * 32; t += 256) {
            int r = t >> 5; int c4 = (t & 31) * 4;
            size_t src = ((size_t)b * SS + kb * 64 + r) * (HH * DD) + (size_t)h * DD + c4;
            *(float4*)&Ks[r * FA_KPAD + c4] = *(const float4*)&kbuf[src];
            *(float4*)&Vs[r * 128 + c4]     = *(const float4*)&vbuf[src];
        }
        __syncthreads();

        float s0[8], s1[8];
#pragma unroll
        for (int i = 0; i < 8; i++) { s0[i] = 0.f; s1[i] = 0.f; }
#pragma unroll 4
        for (int d = 0; d < 128; d += 4) {
            float4 k0 = *(const float4*)&Ks[j0 * FA_KPAD + d];
            float4 k1 = *(const float4*)&Ks[j1 * FA_KPAD + d];
#pragma unroll
            for (int i = 0; i < 8; i++) {
                float4 q = *(const float4*)&Qs[(r0 + i) * 128 + d];
                s0[i] += q.x * k0.x + q.y * k0.y + q.z * k0.z + q.w * k0.w;
                s1[i] += q.x * k1.x + q.y * k1.y + q.z * k1.z + q.w * k1.w;
            }
        }

        const bool diag = (kb == qb);
#pragma unroll
        for (int i = 0; i < 8; i++) {
            float a0 = s0[i], a1 = s1[i];
            if (diag) {
                int q_glob = qb * 64 + r0 + i;
                const float* mrow = &mask[((size_t)b * SS + q_glob) * SS + kb * 64];
                a0 += mrow[j0];
                a1 += mrow[j1];
            }
            float mx = fmaxf(a0, a1);
#pragma unroll
            for (int off = 16; off; off >>= 1)
                mx = fmaxf(mx, __shfl_xor_sync(0xffffffff, mx, off));
            float m_new = fmaxf(m_old[i], mx);
            float p0 = __expf(a0 - m_new);
            float p1 = __expf(a1 - m_new);
            float ls = p0 + p1;
#pragma unroll
            for (int off = 16; off; off >>= 1)
                ls += __shfl_xor_sync(0xffffffff, ls, off);
            float alpha = __expf(m_old[i] - m_new);
            lsum[i] = lsum[i] * alpha + ls;
            m_old[i] = m_new;
#pragma unroll
            for (int c = 0; c < 4; c++) O[i][c] *= alpha;
            Pw[i * FA_PPAD + j0] = p0;
            Pw[i * FA_PPAD + j1] = p1;
        }
        __syncwarp();

#pragma unroll 2
        for (int j = 0; j < 64; j += 4) {
            float4 v0 = *(const float4*)&Vs[(j + 0) * 128 + l * 4];
            float4 v1 = *(const float4*)&Vs[(j + 1) * 128 + l * 4];
            float4 v2 = *(const float4*)&Vs[(j + 2) * 128 + l * 4];
            float4 v3 = *(const float4*)&Vs[(j + 3) * 128 + l * 4];
#pragma unroll
            for (int i = 0; i < 8; i++) {
                float4 p = *(const float4*)&Pw[i * FA_PPAD + j];
                O[i][0] += p.x * v0.x + p.y * v1.x + p.z * v2.x + p.w * v3.x;
                O[i][1] += p.x * v0.y + p.y * v1.y + p.z * v2.y + p.w * v3.y;
                O[i][2] += p.x * v0.z + p.y * v1.z + p.z * v2.z + p.w * v3.z;
                O[i][3] += p.x * v0.w + p.y * v1.w + p.z * v2.w + p.w * v3.w;
            }
        }
    }

#pragma unroll
    for (int i = 0; i < 8; i++) {
        float inv = 1.0f / lsum[i];
        int q_glob = qb * 64 + r0 + i;
        float4 v;
        v.x = O[i][0] * inv; v.y = O[i][1] * inv;
        v.z = O[i][2] * inv; v.w = O[i][3] * inv;
        *(float4*)&attn_out[(((size_t)b * SS + q_glob) * HH + h) * DD + l * 4] = v;
    }
}

// ---------------- launch ----------------------------------------------------
extern "C" void kernel_launch(void* const* d_in, const int* in_sizes, int n_in,
                              void* d_out, int out_size) {
    const float* x      = (const float*)d_in[0];
    const float* f_r    = (const float*)d_in[1];
    const float* f_i    = (const float*)d_in[2];
    const float* mask   = (const float*)d_in[3];
    const float* W_qkv  = (const float*)d_in[4];
    const float* b_qkv  = (const float*)d_in[5];
    const float* W_o    = (const float*)d_in[6];

    float* out   = (float*)d_out;
    float* out_k = out   + (size_t)BB * SS * NSTATE;
    float* out_v = out_k + (size_t)BB * SS * HH * DD;

    float* qkv  = nullptr; cudaGetSymbolAddress((void**)&qkv,  g_qkv);
    float* attn = nullptr; cudaGetSymbolAddress((void**)&attn, g_attn);

    const int M = BB * SS;   // 4096

    cudaFuncSetAttribute(flash_attn, cudaFuncAttributeMaxDynamicSharedMemorySize,
                         FA_SMEM_BYTES);

    // 1) QKV projection: [4096,6144] = x @ W_qkv^T + b  (tf32 mma.sync)
    gemm_mma<<<dim3(QKV_W / 128, M / 128), 256>>>(x, W_qkv, b_qkv, qkv,
                                                  M, QKV_W, NSTATE);

    // 2) RoPE q,k; scatter k,v to output
    rope_scatter<<<(BB * SS * HH * 64) / 256, 256>>>(qkv, f_r, f_i, out_k, out_v);

    // 3) attention (causal block skip)
    flash_attn<<<dim3(SS / 64, HH, BB), 256, FA_SMEM_BYTES>>>(qkv, out_k, out_v,
                                                              mask, attn);

    // 4) output projection: [4096,2048] = attn @ W_o^T  (tf32 mma.sync)
    gemm_mma<<<dim3(NSTATE / 128, M / 128), 256>>>(attn, W_o, nullptr, out,
                                                   M, NSTATE, NSTATE);
}

// round 4
// speedup vs baseline: 3.1122x; 1.3778x over previous
#include <cuda_runtime.h>
#include <cuda_bf16.h>
#include <cstdint>
#include <math.h>

// Problem constants
#define BB 2
#define SS 2048
#define HH 16
#define DD 128
#define NSTATE 2048
#define QKV_W (3*HH*DD)   // 6144

// ---------------- scratch (device globals; no runtime alloc) ----------------
__device__ float g_qkv[(size_t)BB * SS * QKV_W];    // [B,S,6144]
__device__ float g_attn[(size_t)BB * SS * HH * DD]; // [B,S,H,D]

// ---------------- helpers ----------------------------------------------------
__device__ __forceinline__ uint32_t tf32_rna(float x) {
    uint32_t r; asm("cvt.rna.tf32.f32 %0, %1;" : "=r"(r) : "f"(x)); return r;
}
__device__ __forceinline__ void mma_tf32_16x8x8(float* c, const uint32_t* a,
                                                const uint32_t* b) {
    asm volatile(
        "mma.sync.aligned.m16n8k8.row.col.f32.tf32.tf32.f32 "
        "{%0,%1,%2,%3}, {%4,%5,%6,%7}, {%8,%9}, {%0,%1,%2,%3};\n"
        : "+f"(c[0]), "+f"(c[1]), "+f"(c[2]), "+f"(c[3])
        : "r"(a[0]), "r"(a[1]), "r"(a[2]), "r"(a[3]), "r"(b[0]), "r"(b[1]));
}

// ============================================================================
// tf32 mma.sync GEMM (NT): C[m,n] = sum_k A[m,k]*B[n,k] (+bias[n])
// Block tile 128x128x16, 8 warps (4x2), warp tile 32x64, double-buffered smem.
// ============================================================================
#define TPAD 20

__global__ __launch_bounds__(256, 2)
void gemm_mma(const float* __restrict__ A, const float* __restrict__ B,
              const float* __restrict__ bias, float* __restrict__ C,
              int M, int N, int K) {
    __shared__ uint32_t As[2][128 * TPAD];
    __shared__ uint32_t Bs[2][128 * TPAD];

    const int tid = threadIdx.x;
    const int w = tid >> 5, l = tid & 31;
    const int lr = l >> 2, lc = l & 3;
    const int wm = w >> 1, wn = w & 1;
    const int m0 = blockIdx.y * 128, n0 = blockIdx.x * 128;

    const int row = tid >> 2;
    const int c4  = (tid & 3) * 4;

    float acc[2][8][4];
#pragma unroll
    for (int mt = 0; mt < 2; mt++)
#pragma unroll
        for (int nt = 0; nt < 8; nt++)
#pragma unroll
            for (int i = 0; i < 4; i++) acc[mt][nt][i] = 0.f;

    float4 pa0, pa1, pb0, pb1;
    const int NC = K / 16;

    pa0 = *(const float4*)&A[(size_t)(m0 + row) * K + c4];
    pa1 = *(const float4*)&A[(size_t)(m0 + row + 64) * K + c4];
    pb0 = *(const float4*)&B[(size_t)(n0 + row) * K + c4];
    pb1 = *(const float4*)&B[(size_t)(n0 + row + 64) * K + c4];
    {
        uint32_t* a = As[0]; uint32_t* b = Bs[0];
        a[row * TPAD + c4 + 0] = tf32_rna(pa0.x); a[row * TPAD + c4 + 1] = tf32_rna(pa0.y);
        a[row * TPAD + c4 + 2] = tf32_rna(pa0.z); a[row * TPAD + c4 + 3] = tf32_rna(pa0.w);
        a[(row + 64) * TPAD + c4 + 0] = tf32_rna(pa1.x); a[(row + 64) * TPAD + c4 + 1] = tf32_rna(pa1.y);
        a[(row + 64) * TPAD + c4 + 2] = tf32_rna(pa1.z); a[(row + 64) * TPAD + c4 + 3] = tf32_rna(pa1.w);
        b[row * TPAD + c4 + 0] = tf32_rna(pb0.x); b[row * TPAD + c4 + 1] = tf32_rna(pb0.y);
        b[row * TPAD + c4 + 2] = tf32_rna(pb0.z); b[row * TPAD + c4 + 3] = tf32_rna(pb0.w);
        b[(row + 64) * TPAD + c4 + 0] = tf32_rna(pb1.x); b[(row + 64) * TPAD + c4 + 1] = tf32_rna(pb1.y);
        b[(row + 64) * TPAD + c4 + 2] = tf32_rna(pb1.z); b[(row + 64) * TPAD + c4 + 3] = tf32_rna(pb1.w);
    }
    __syncthreads();

    const int aBase = (wm * 32 + lr) * TPAD;
    const int bBase = (wn * 64 + lr) * TPAD;

    for (int c = 0; c < NC; c++) {
        const int buf = c & 1;
        if (c + 1 < NC) {
            const int k0 = (c + 1) * 16;
            pa0 = *(const float4*)&A[(size_t)(m0 + row) * K + k0 + c4];
            pa1 = *(const float4*)&A[(size_t)(m0 + row + 64) * K + k0 + c4];
            pb0 = *(const float4*)&B[(size_t)(n0 + row) * K + k0 + c4];
            pb1 = *(const float4*)&B[(size_t)(n0 + row + 64) * K + k0 + c4];
        }

        const uint32_t* __restrict__ a_s = As[buf];
        const uint32_t* __restrict__ b_s = Bs[buf];
#pragma unroll
        for (int kk = 0; kk < 16; kk += 8) {
            uint32_t af[2][4];
#pragma unroll
            for (int mt = 0; mt < 2; mt++) {
                int o = aBase + mt * (16 * TPAD) + kk + lc;
                af[mt][0] = a_s[o];
                af[mt][1] = a_s[o + 8 * TPAD];
                af[mt][2] = a_s[o + 4];
                af[mt][3] = a_s[o + 8 * TPAD + 4];
            }
            uint32_t bf[8][2];
#pragma unroll
            for (int nt = 0; nt < 8; nt++) {
                int o = bBase + nt * (8 * TPAD) + kk + lc;
                bf[nt][0] = b_s[o];
                bf[nt][1] = b_s[o + 4];
            }
#pragma unroll
            for (int mt = 0; mt < 2; mt++)
#pragma unroll
                for (int nt = 0; nt < 8; nt++)
                    mma_tf32_16x8x8(acc[mt][nt], af[mt], bf[nt]);
        }
        __syncthreads();

        if (c + 1 < NC) {
            const int nb = (c + 1) & 1;
            uint32_t* a = As[nb]; uint32_t* b = Bs[nb];
            a[row * TPAD + c4 + 0] = tf32_rna(pa0.x); a[row * TPAD + c4 + 1] = tf32_rna(pa0.y);
            a[row * TPAD + c4 + 2] = tf32_rna(pa0.z); a[row * TPAD + c4 + 3] = tf32_rna(pa0.w);
            a[(row + 64) * TPAD + c4 + 0] = tf32_rna(pa1.x); a[(row + 64) * TPAD + c4 + 1] = tf32_rna(pa1.y);
            a[(row + 64) * TPAD + c4 + 2] = tf32_rna(pa1.z); a[(row + 64) * TPAD + c4 + 3] = tf32_rna(pa1.w);
            b[row * TPAD + c4 + 0] = tf32_rna(pb0.x); b[row * TPAD + c4 + 1] = tf32_rna(pb0.y);
            b[row * TPAD + c4 + 2] = tf32_rna(pb0.z); b[row * TPAD + c4 + 3] = tf32_rna(pb0.w);
            b[(row + 64) * TPAD + c4 + 0] = tf32_rna(pb1.x); b[(row + 64) * TPAD + c4 + 1] = tf32_rna(pb1.y);
            b[(row + 64) * TPAD + c4 + 2] = tf32_rna(pb1.z); b[(row + 64) * TPAD + c4 + 3] = tf32_rna(pb1.w);
            __syncthreads();
        }
    }

#pragma unroll
    for (int mt = 0; mt < 2; mt++) {
        int m = m0 + wm * 32 + mt * 16 + lr;
#pragma unroll
        for (int nt = 0; nt < 8; nt++) {
            int n = n0 + wn * 64 + nt * 8 + lc * 2;
            float bx = 0.f, by = 0.f;
            if (bias) { bx = bias[n]; by = bias[n + 1]; }
            float2 v0 = { acc[mt][nt][0] + bx, acc[mt][nt][1] + by };
            float2 v1 = { acc[mt][nt][2] + bx, acc[mt][nt][3] + by };
            *(float2*)&C[(size_t)m * N + n] = v0;
            *(float2*)&C[(size_t)(m + 8) * N + n] = v1;
        }
    }
}

// ---------------- RoPE (q in place, k -> out_k), v copy ---------------------
__global__ void rope_scatter(float* __restrict__ qkv,
                             const float* __restrict__ f_r,
                             const float* __restrict__ f_i,
                             float* __restrict__ out_k,
                             float* __restrict__ out_v) {
    int idx = blockIdx.x * blockDim.x + threadIdx.x;
    if (idx >= BB * SS * HH * 64) return;
    int d2 = idx & 63;
    int h  = (idx >> 6) & (HH - 1);
    int bs = idx >> 10;

    float fr = f_r[(size_t)bs * 64 + d2];
    float fi = f_i[(size_t)bs * 64 + d2];

    size_t base = (size_t)bs * QKV_W;
    size_t qi = base + (size_t)h * DD + d2;
    float xr = qkv[qi], xi = qkv[qi + 64];
    qkv[qi]      = xr * fr - xi * fi;
    qkv[qi + 64] = xr * fi + xi * fr;

    size_t ki = base + (size_t)HH * DD + (size_t)h * DD + d2;
    xr = qkv[ki]; xi = qkv[ki + 64];
    size_t ko = ((size_t)bs * HH + h) * DD + d2;
    out_k[ko]      = xr * fr - xi * fi;
    out_k[ko + 64] = xr * fi + xi * fr;

    size_t vi = base + (size_t)2 * HH * DD + (size_t)h * DD + d2;
    out_v[ko]      = qkv[vi];
    out_v[ko + 64] = qkv[vi + 64];
}

// ============================================================================
// Flash attention on tf32 mma.sync. BM=128 (8 warps x 16 rows), BN=64, D=128.
// Q,K tf32 in smem; V staged transposed (Vt[d][j]); P via per-warp smem.
// Causal block skip; gmem mask applied on the two diagonal blocks only.
// ============================================================================
#define QP 132
#define KP 132
#define VP 68
#define PP 68
#define FA_WORDS (128*QP + 64*KP + 128*VP + 128*PP)
#define FA_BYTES (FA_WORDS * 4)

__global__ __launch_bounds__(256, 1)
void flash_attn(const float* __restrict__ qkv,
                const float* __restrict__ kbuf,
                const float* __restrict__ vbuf,
                const float* __restrict__ mask,
                float* __restrict__ attn_out) {
    extern __shared__ uint32_t smw[];
    uint32_t* Qs = smw;                 // [128][QP] tf32
    uint32_t* Ks = Qs + 128 * QP;       // [64][KP]  tf32
    uint32_t* Vt = Ks + 64 * KP;        // [128][VP] tf32 (V transposed: [d][j])
    uint32_t* Ps = Vt + 128 * VP;       // [128][PP] tf32 (P, row-major)

    const int qb = blockIdx.x, h = blockIdx.y, b = blockIdx.z;
    const int tid = threadIdx.x, w = tid >> 5, l = tid & 31;
    const int lr = l >> 2, lc = l & 3;
    const float scale = 0.08838834764831845f;   // 1/sqrt(128)

    // ---- load Q tile (prescaled, tf32) ----
    for (int t = tid; t < 128 * 32; t += 256) {
        int r = t >> 5, c4 = (t & 31) * 4;
        float4 v = *(const float4*)&qkv[((size_t)b * SS + qb * 128 + r) * QKV_W
                                        + h * DD + c4];
        uint32_t* dst = &Qs[r * QP + c4];
        dst[0] = tf32_rna(v.x * scale); dst[1] = tf32_rna(v.y * scale);
        dst[2] = tf32_rna(v.z * scale); dst[3] = tf32_rna(v.w * scale);
    }

    float O[16][4];
#pragma unroll
    for (int nt = 0; nt < 16; nt++)
#pragma unroll
        for (int i = 0; i < 4; i++) O[nt][i] = 0.f;
    float m_lo = -INFINITY, m_hi = -INFINITY, l_lo = 0.f, l_hi = 0.f;

    const int aQ = (w * 16 + lr) * QP;           // warp's Q fragment base
    const int aP = (w * 16 + lr) * PP;
    const int nKV = 2 * qb + 2;                  // causal block count

    for (int kb = 0; kb < nKV; kb++) {
        __syncthreads();   // prior iter's Ks/Vt reads complete
        // ---- load K (row-major) and V (transposed), tf32 ----
        for (int t = tid; t < 64 * 32; t += 256) {
            int r = t >> 5, c4 = (t & 31) * 4;
            size_t src = ((size_t)b * SS + kb * 64 + r) * (HH * DD)
                       + (size_t)h * DD + c4;
            float4 kv = *(const float4*)&kbuf[src];
            uint32_t* kd = &Ks[r * KP + c4];
            kd[0] = tf32_rna(kv.x); kd[1] = tf32_rna(kv.y);
            kd[2] = tf32_rna(kv.z); kd[3] = tf32_rna(kv.w);
            float4 vv = *(const float4*)&vbuf[src];
            Vt[(c4 + 0) * VP + r] = tf32_rna(vv.x);
            Vt[(c4 + 1) * VP + r] = tf32_rna(vv.y);
            Vt[(c4 + 2) * VP + r] = tf32_rna(vv.z);
            Vt[(c4 + 3) * VP + r] = tf32_rna(vv.w);
        }
        __syncthreads();

        // ---- S = Q K^T : m16 x n64 x k128 per warp ----
        float S[8][4];
#pragma unroll
        for (int nt = 0; nt < 8; nt++)
#pragma unroll
            for (int i = 0; i < 4; i++) S[nt][i] = 0.f;
#pragma unroll
        for (int ks = 0; ks < 16; ks++) {
            const int ko = ks * 8 + lc;
            uint32_t af[4];
            af[0] = Qs[aQ + ko];
            af[1] = Qs[aQ + 8 * QP + ko];
            af[2] = Qs[aQ + ko + 4];
            af[3] = Qs[aQ + 8 * QP + ko + 4];
#pragma unroll
            for (int nt = 0; nt < 8; nt++) {
                uint32_t bf[2];
                bf[0] = Ks[(nt * 8 + lr) * KP + ko];
                bf[1] = Ks[(nt * 8 + lr) * KP + ko + 4];
                mma_tf32_16x8x8(S[nt], af, bf);
            }
        }

        // ---- diagonal blocks: add gmem mask ----
        if (kb >= 2 * qb) {
            const int m_glo = qb * 128 + w * 16 + lr;
            const float* mr0 = &mask[((size_t)b * SS + m_glo) * SS + kb * 64];
            const float* mr1 = mr0 + 8 * SS;
#pragma unroll
            for (int nt = 0; nt < 8; nt++) {
                float2 q0 = *(const float2*)&mr0[nt * 8 + lc * 2];
                float2 q1 = *(const float2*)&mr1[nt * 8 + lc * 2];
                S[nt][0] += q0.x; S[nt][1] += q0.y;
                S[nt][2] += q1.x; S[nt][3] += q1.y;
            }
        }

        // ---- online softmax (rows lr and lr+8) ----
        float bm_lo = -INFINITY, bm_hi = -INFINITY;
#pragma unroll
        for (int nt = 0; nt < 8; nt++) {
            bm_lo = fmaxf(bm_lo, fmaxf(S[nt][0], S[nt][1]));
            bm_hi = fmaxf(bm_hi, fmaxf(S[nt][2], S[nt][3]));
        }
        bm_lo = fmaxf(bm_lo, __shfl_xor_sync(0xffffffff, bm_lo, 1));
        bm_lo = fmaxf(bm_lo, __shfl_xor_sync(0xffffffff, bm_lo, 2));
        bm_hi = fmaxf(bm_hi, __shfl_xor_sync(0xffffffff, bm_hi, 1));
        bm_hi = fmaxf(bm_hi, __shfl_xor_sync(0xffffffff, bm_hi, 2));
        float mn_lo = fmaxf(m_lo, bm_lo);
        float mn_hi = fmaxf(m_hi, bm_hi);

        float rs_lo = 0.f, rs_hi = 0.f;
#pragma unroll
        for (int nt = 0; nt < 8; nt++) {
            S[nt][0] = __expf(S[nt][0] - mn_lo);
            S[nt][1] = __expf(S[nt][1] - mn_lo);
            S[nt][2] = __expf(S[nt][2] - mn_hi);
            S[nt][3] = __expf(S[nt][3] - mn_hi);
            rs_lo += S[nt][0] + S[nt][1];
            rs_hi += S[nt][2] + S[nt][3];
        }
        rs_lo += __shfl_xor_sync(0xffffffff, rs_lo, 1);
        rs_lo += __shfl_xor_sync(0xffffffff, rs_lo, 2);
        rs_hi += __shfl_xor_sync(0xffffffff, rs_hi, 1);
        rs_hi += __shfl_xor_sync(0xffffffff, rs_hi, 2);

        float al_lo = __expf(m_lo - mn_lo);
        float al_hi = __expf(m_hi - mn_hi);
        l_lo = l_lo * al_lo + rs_lo;
        l_hi = l_hi * al_hi + rs_hi;
        m_lo = mn_lo; m_hi = mn_hi;
#pragma unroll
        for (int nt = 0; nt < 16; nt++) {
            O[nt][0] *= al_lo; O[nt][1] *= al_lo;
            O[nt][2] *= al_hi; O[nt][3] *= al_hi;
        }

        // ---- stage P (warp-local) as tf32 ----
#pragma unroll
        for (int nt = 0; nt < 8; nt++) {
            int cw = nt * 8 + lc * 2;
            uint2 p0 = { tf32_rna(S[nt][0]), tf32_rna(S[nt][1]) };
            uint2 p1 = { tf32_rna(S[nt][2]), tf32_rna(S[nt][3]) };
            *(uint2*)&Ps[aP + cw] = p0;
            *(uint2*)&Ps[aP + 8 * PP + cw] = p1;
        }
        __syncwarp();

        // ---- O += P V : m16 x n128 x k64 per warp ----
#pragma unroll
        for (int ks = 0; ks < 8; ks++) {
            const int ko = ks * 8 + lc;
            uint32_t af[4];
            af[0] = Ps[aP + ko];
            af[1] = Ps[aP + 8 * PP + ko];
            af[2] = Ps[aP + ko + 4];
            af[3] = Ps[aP + 8 * PP + ko + 4];
#pragma unroll
            for (int nt = 0; nt < 16; nt++) {
                uint32_t bf[2];
                bf[0] = Vt[(nt * 8 + lr) * VP + ko];
                bf[1] = Vt[(nt * 8 + lr) * VP + ko + 4];
                mma_tf32_16x8x8(O[nt], af, bf);
            }
        }
        __syncwarp();   // Ps reads done before next iter overwrites
    }

    // ---- epilogue: normalize, write [B,S,H,D] ----
    const float inv_lo = 1.0f / l_lo, inv_hi = 1.0f / l_hi;
    const int m0 = qb * 128 + w * 16 + lr;
#pragma unroll
    for (int nt = 0; nt < 16; nt++) {
        int d = nt * 8 + lc * 2;
        float2 v0 = { O[nt][0] * inv_lo, O[nt][1] * inv_lo };
        float2 v1 = { O[nt][2] * inv_hi, O[nt][3] * inv_hi };
        *(float2*)&attn_out[(((size_t)b * SS + m0) * HH + h) * DD + d] = v0;
        *(float2*)&attn_out[(((size_t)b * SS + m0 + 8) * HH + h) * DD + d] = v1;
    }
}

// ---------------- launch ----------------------------------------------------
extern "C" void kernel_launch(void* const* d_in, const int* in_sizes, int n_in,
                              void* d_out, int out_size) {
    const float* x      = (const float*)d_in[0];
    const float* f_r    = (const float*)d_in[1];
    const float* f_i    = (const float*)d_in[2];
    const float* mask   = (const float*)d_in[3];
    const float* W_qkv  = (const float*)d_in[4];
    const float* b_qkv  = (const float*)d_in[5];
    const float* W_o    = (const float*)d_in[6];

    float* out   = (float*)d_out;
    float* out_k = out   + (size_t)BB * SS * NSTATE;
    float* out_v = out_k + (size_t)BB * SS * HH * DD;

    float* qkv  = nullptr; cudaGetSymbolAddress((void**)&qkv,  g_qkv);
    float* attn = nullptr; cudaGetSymbolAddress((void**)&attn, g_attn);

    const int M = BB * SS;   // 4096

    cudaFuncSetAttribute(flash_attn, cudaFuncAttributeMaxDynamicSharedMemorySize,
                         FA_BYTES);

    // 1) QKV projection (tf32 mma.sync)
    gemm_mma<<<dim3(QKV_W / 128, M / 128), 256>>>(x, W_qkv, b_qkv, qkv,
                                                  M, QKV_W, NSTATE);
    // 2) RoPE q,k; scatter k,v to output
    rope_scatter<<<(BB * SS * HH * 64) / 256, 256>>>(qkv, f_r, f_i, out_k, out_v);
    // 3) attention (tf32 mma, causal block skip)
    flash_attn<<<dim3(SS / 128, HH, BB), 256, FA_BYTES>>>(qkv, out_k, out_v,
                                                          mask, attn);
    // 4) output projection (tf32 mma.sync)
    gemm_mma<<<dim3(NSTATE / 128, M / 128), 256>>>(attn, W_o, nullptr, out,
                                                   M, NSTATE, NSTATE);
}